// round 16
// baseline (speedup 1.0000x reference)
#include <cuda_runtime.h>
#include <math.h>

// ---------------- problem constants ----------------
#define Nn    20000
#define Ee    640000
#define Pp    27
#define Mm    5000
#define MAXNb 64
#define KIN   64
#define PIN   (Pp * KIN)      // 1728
#define R2c   0.01f
#define NC    512             // 8x8x8 spatial cells
#define CL    2               // FPS cluster size (half the cloud per CTA)
#define SLAB_MAX 10560        // max points per half (mean 10000)

// output section offsets (flattened float32 tuple concat)
#define SEC_X     0
#define SEC_COL   320000
#define SEC_ROW   640000
#define SEC_POS   960000
#define SEC_BATCH 975000
#define SEC_EA    980000

// ---------------- persistent device scratch ----------------
__device__ __align__(16) float4 g_pos4[Nn];   // x,y,z, |p|^2
__device__ int    g_idx[Mm];
__device__ int    g_pcell[Nn];
__device__ int    g_cellcnt[NC];
__device__ int    g_cellstart[NC + 1];
__device__ int    g_cellfill[NC];
__device__ __align__(16) float4 g_spos[Nn];   // cell-sorted: x,y,z, orig idx bits
__device__ __align__(16) float g_accN[(size_t)Nn * PIN];  // 138 MB, all nodes
__device__ float  g_degN[Nn];

// ---------------- launch 1: pos4 + cell id + histogram (single block) ----------------
__global__ void __launch_bounds__(1024) prep1b_kernel(const float* __restrict__ pos) {
    int tid = threadIdx.x;
    if (tid < NC) g_cellcnt[tid] = 0;
    __syncthreads();
    for (int i = tid; i < Nn; i += 1024) {
        float x = pos[3 * i], y = pos[3 * i + 1], z = pos[3 * i + 2];
        float an = __fadd_rn(__fadd_rn(__fmul_rn(x, x), __fmul_rn(y, y)),
                             __fmul_rn(z, z));
        g_pos4[i] = make_float4(x, y, z, an);
        int cx = min((int)(x * 8.0f), 7);
        int cy = min((int)(y * 8.0f), 7);
        int cz = min((int)(z * 8.0f), 7);
        int cid = (cx << 6) | (cy << 3) | cz;
        g_pcell[i] = cid;
        atomicAdd(&g_cellcnt[cid], 1);
    }
}

// ---------------- launch 2: exclusive scan of cell counts ----------------
__global__ void cell_scan_kernel() {
    __shared__ int sh[NC];
    int tid = threadIdx.x;
    int v = g_cellcnt[tid];
    sh[tid] = v;
    __syncthreads();
    for (int o = 1; o < NC; o <<= 1) {
        int t = (tid >= o) ? sh[tid - o] : 0;
        __syncthreads();
        sh[tid] += t;
        __syncthreads();
    }
    g_cellstart[tid + 1] = sh[tid];
    g_cellfill[tid] = sh[tid] - v;
    if (tid == 0) g_cellstart[0] = 0;
}

// ---------------- launch 3: cell scatter + zero acc/deg (fused) ----------------
#define ZB 33750   // 33750*256 float4 = Nn*PIN floats
__global__ void scatter_zero_kernel(const float* __restrict__ pos) {
    int i = blockIdx.x * blockDim.x + threadIdx.x;
    if (i < Nn) {
        int cid = g_pcell[i];
        int off = atomicAdd(&g_cellfill[cid], 1);
        g_spos[off] = make_float4(pos[3 * i], pos[3 * i + 1], pos[3 * i + 2],
                                  __int_as_float(i));
        g_degN[i] = 0.0f;
    }
    reinterpret_cast<float4*>(g_accN)[i] = make_float4(0.f, 0.f, 0.f, 0.f);
}

// ---------------- FPS cluster helpers ----------------
__device__ __forceinline__ unsigned smem_u32(const void* p) {
    unsigned a;
    asm("{ .reg .u64 t; cvta.to.shared.u64 t, %1; cvt.u32.u64 %0, t; }"
        : "=r"(a) : "l"(p));
    return a;
}
__device__ __forceinline__ unsigned cl_rank() {
    unsigned r;
    asm("mov.u32 %0, %%cluster_ctarank;" : "=r"(r));
    return r;
}
#define CL_SYNC() do { \
    asm volatile("barrier.cluster.arrive.aligned;" ::: "memory"); \
    asm volatile("barrier.cluster.wait.aligned;" ::: "memory"); } while (0)

// HW-sleep wait: hinted try_wait (suspend), retry loop also hinted.
#define MBAR_WAIT_CLUSTER(mbar, par) do { \
    unsigned _done; \
    asm volatile("{\n\t.reg .pred p;\n\t" \
        "mbarrier.try_wait.parity.acquire.cluster.shared::cta.b64 p, [%1], %2, 0x989680;\n\t" \
        "selp.b32 %0, 1, 0, p;\n\t}" \
        : "=r"(_done) : "r"(mbar), "r"(par) : "memory"); \
    if (!_done) { \
        asm volatile("{\n\t.reg .pred P1;\n\t" \
            "WAITC_%=:\n\t" \
            "mbarrier.try_wait.parity.acquire.cluster.shared::cta.b64 P1, [%0], %1, 0x989680;\n\t" \
            "@P1 bra.uni DONEC_%=;\n\t" \
            "bra.uni WAITC_%=;\n\t" \
            "DONEC_%=:\n\t}" :: "r"(mbar), "r"(par) : "memory"); \
    } } while (0)

// ---------------- FPS SMEM layout (2-CTA, half cloud resident) ----------------
#define OFF_PT     0u                         // SLAB_MAX*16 = 168960
#define OFF_MIND   168960u                    // SLAB_MAX*4  = 42240
#define OFF_CST    211200u                    // 257*4 -> pad 1040
#define OFF_SKEY   212240u                    // 2 bufs * 32 slots * u64 = 512
#define OFF_SPOS   212752u                    // 2 bufs * 32 slots * float4 = 1024
#define OFF_MBAR   213776u                    // 2 mbarriers = 16
#define FPS_SMEM   213792u

// ---------------- FPS body: 2-CTA cluster, warp-direct exchange, NO block barrier ----
__device__ void fps_cluster(unsigned char* s_raw) {
    float4*             s_pt   = (float4*)(s_raw + OFF_PT);
    float*              s_mind = (float*)(s_raw + OFF_MIND);
    int*                s_cst  = (int*)(s_raw + OFF_CST);
    unsigned long long* s_skey = (unsigned long long*)(s_raw + OFF_SKEY);
    float4*             s_spos = (float4*)(s_raw + OFF_SPOS);

    const int tid = threadIdx.x, lane = tid & 31, wid = tid >> 5;
    const unsigned FULL = 0xffffffffu;
    const float INF = __int_as_float(0x7f800000);
    const unsigned rank = cl_rank();
    const int slotid = (int)rank * 16 + wid;      // this warp's global slot

    const unsigned mbar_l = smem_u32(s_raw + OFF_MBAR);
    const unsigned skey_l = smem_u32(s_raw + OFF_SKEY);
    const unsigned spos_l = smem_u32(s_raw + OFF_SPOS);
    unsigned mbar_r, skey_r, spos_r;              // peer addresses (hoisted mapa)
    asm("mapa.shared::cluster.u32 %0, %1, %2;" : "=r"(mbar_r) : "r"(mbar_l), "r"(rank ^ 1u));
    asm("mapa.shared::cluster.u32 %0, %1, %2;" : "=r"(skey_r) : "r"(skey_l), "r"(rank ^ 1u));
    asm("mapa.shared::cluster.u32 %0, %1, %2;" : "=r"(spos_r) : "r"(spos_l), "r"(rank ^ 1u));

    // ---- per-lane owned cell (bijective balanced map: 16 cells/warp) ----
    int l   = lane & 15;
    int cx4 = l >> 2, cyi = l & 3;
    int cz  = ((wid & 7) - 2 * cx4) & 7;
    int par0 = ((wid >> 3) ^ cx4) & 1;
    int cy  = 2 * cyi + par0;
    int cid = (cx4 << 6) | (cy << 3) | cz;
    const float lx = (float)((int)rank * 4 + cx4) * 0.125f;
    const float ly = (float)cy * 0.125f;
    const float lz = (float)cz * 0.125f;

    // ---- init: load half-cloud into SMEM ----
    int base  = g_cellstart[rank * 256];
    int count = min(g_cellstart[rank * 256 + 256] - base, SLAB_MAX);
    if (tid <= 256)
        s_cst[tid] = min(g_cellstart[rank * 256 + tid] - base, SLAB_MAX);
    for (int i = tid; i < count; i += 512) {
        s_pt[i] = g_spos[base + i];
        s_mind[i] = INF;
    }
    __syncthreads();
    const int st_l = s_cst[cid], en_l = s_cst[cid + 1];
    // register cell state: key (hi=ub bits, lo=~idx) + cached winner position
    unsigned long long ukey =
        (lane < 16 && en_l > st_l) ? (0x7f800000ULL << 32) : 0ULL;
    float uwx = 0.f, uwy = 0.f, uwz = 0.f;        // set on first update (all cells
                                                  // are active at t=0: lb2 < INF)
    if (tid == 0) {
        asm volatile("mbarrier.init.shared.b64 [%0], %1;" :: "r"(mbar_l),     "r"(32) : "memory");
        asm volatile("mbarrier.init.shared.b64 [%0], %1;" :: "r"(mbar_l + 8), "r"(32) : "memory");
        if (rank == 0) g_idx[0] = 0;
    }
    __syncthreads();
    CL_SYNC();                         // mbarriers + tiles visible cluster-wide

    float4 q0 = g_pos4[0];
    float qx = q0.x, qy = q0.y, qz = q0.z;

    for (int t = 0; t < Mm - 1; ++t) {
        const int buf = t & 1;
        const int parity = (t >> 1) & 1;
        // ---- activity over this warp's 16 register cells ----
        float dx = fmaxf(fmaxf(lx - qx, qx - (lx + 0.125f)), 0.0f);
        float dy = fmaxf(fmaxf(ly - qy, qy - (ly + 0.125f)), 0.0f);
        float dz = fmaxf(fmaxf(lz - qz, qz - (lz + 0.125f)), 0.0f);
        float lb2 = dx * dx + dy * dy + dz * dz;
        float ub = __uint_as_float((unsigned)(ukey >> 32));
        bool act = (lane < 16) && (lb2 * 0.99999f < ub);
        unsigned bal = __ballot_sync(FULL, act);
        // ---- update active cells (whole warp per cell; keys/pos in regs) ----
        while (bal) {
            int i = __ffs(bal) - 1; bal &= bal - 1;
            int st = __shfl_sync(FULL, st_l, i);
            int en = __shfl_sync(FULL, en_l, i);
            float bv = -1.0f; int bidx = 0x7FFFFFFF;
            float bx = 0.f, by = 0.f, bz = 0.f;
            for (int k = st + lane; k < en; k += 32) {
                float4 p = s_pt[k];
                float ddx = p.x - qx, ddy = p.y - qy, ddz = p.z - qz;
                float d2 = __fadd_rn(__fadd_rn(__fmul_rn(ddx, ddx),
                                               __fmul_rn(ddy, ddy)),
                                     __fmul_rn(ddz, ddz));
                float nm = fminf(s_mind[k], d2);
                s_mind[k] = nm;
                int oi = __float_as_int(p.w);
                if (nm > bv || (nm == bv && oi < bidx)) {
                    bv = nm; bidx = oi; bx = p.x; by = p.y; bz = p.z;
                }
            }
            unsigned vb = (bv < 0.f) ? 0u : __float_as_uint(bv);
            unsigned mv = __reduce_max_sync(FULL, vb);
            unsigned ciw = (vb == mv) ? (unsigned)bidx : 0xFFFFFFFFu;
            unsigned mi = __reduce_min_sync(FULL, ciw);
            int wl = __ffs(__ballot_sync(FULL, vb == mv && (unsigned)bidx == mi)) - 1;
            float px = __shfl_sync(FULL, bx, wl);
            float py = __shfl_sync(FULL, by, wl);
            float pz = __shfl_sync(FULL, bz, wl);
            if (lane == i) {                          // owner lane caches in regs
                ukey = ((unsigned long long)mv << 32) |
                       (unsigned long long)(0xFFFFFFFFu - mi);
                uwx = px; uwy = py; uwz = pz;
            }
        }
        // ---- warp best over 32 register keys -> write BOTH CTAs' slots ----
        {
            unsigned hi = (unsigned)(ukey >> 32), lo = (unsigned)ukey;
            unsigned mhi = __reduce_max_sync(FULL, hi);
            unsigned lo2 = (hi == mhi) ? lo : 0u;
            unsigned mlo = __reduce_max_sync(FULL, lo2);
            unsigned long long wbest = ((unsigned long long)mhi << 32) | mlo;
            int wl = __ffs(__ballot_sync(FULL, ukey == wbest)) - 1;
            if (lane == wl) {
                int si = buf * 32 + slotid;
                // local copies (default-release local arrive orders these)
                s_skey[si] = wbest;
                s_spos[si] = make_float4(uwx, uwy, uwz, 0.f);
                // remote copies + release arrive (orders the cluster stores)
                unsigned rk = skey_r + (unsigned)si * 8u;
                unsigned rp = spos_r + (unsigned)si * 16u;
                unsigned long long xy =
                    ((unsigned long long)__float_as_uint(uwy) << 32) |
                    (unsigned long long)__float_as_uint(uwx);
                asm volatile("st.shared::cluster.u64 [%0], %1;" :: "r"(rk), "l"(wbest) : "memory");
                asm volatile("st.shared::cluster.u64 [%0], %1;" :: "r"(rp), "l"(xy) : "memory");
                asm volatile("st.shared::cluster.b32 [%0], %1;"
                             :: "r"(rp + 8), "r"(__float_as_uint(uwz)) : "memory");
                asm volatile("mbarrier.arrive.release.cluster.shared::cluster.b64 _, [%0];"
                             :: "r"(mbar_r + (unsigned)buf * 8u) : "memory");
                asm volatile("mbarrier.arrive.shared.b64 _, [%0];"
                             :: "r"(mbar_l + (unsigned)buf * 8u) : "memory");
            }
        }
        // ---- wait for all 32 warp-arrives (16 local + 16 remote), combine ----
        // Slot-reuse safety: slot[buf] is rewritten at t+2 only after the
        // writer passes wait(t+1), which requires every warp's arrive(t+1),
        // which (program order) follows that warp's combine reads at t.
        MBAR_WAIT_CLUSTER(mbar_l + (unsigned)buf * 8u, parity);
        unsigned long long k = s_skey[buf * 32 + lane];   // 32 contiguous u64
        unsigned hi = (unsigned)(k >> 32), lo = (unsigned)k;
        unsigned mhi = __reduce_max_sync(FULL, hi);
        unsigned lo2 = (hi == mhi) ? lo : 0u;
        unsigned mlo = __reduce_max_sync(FULL, lo2);
        unsigned long long best = ((unsigned long long)mhi << 32) | mlo;
        int b = __ffs(__ballot_sync(FULL, k == best)) - 1;
        float4 wq = s_spos[buf * 32 + b];             // LDS.128 broadcast
        qx = wq.x; qy = wq.y; qz = wq.z;
        if (rank == 0 && tid == 0)
            g_idx[t + 1] = (int)(0xFFFFFFFFu - mlo);
    }

    // ---- teardown: inval mbarriers for graph-replay safety ----
    __syncthreads();
    CL_SYNC();
    if (tid == 0) {
        asm volatile("mbarrier.inval.shared.b64 [%0];" :: "r"(mbar_l)     : "memory");
        asm volatile("mbarrier.inval.shared.b64 [%0];" :: "r"(mbar_l + 8) : "memory");
    }
    __syncthreads();
    CL_SYNC();
}

// ---------------- scatter body: all edges, all nodes, warp per edge ----------------
__device__ void scatter_all(const float* __restrict__ x,
                            const int*   __restrict__ ei,
                            const float* __restrict__ ea,
                            int cta, int nctas) {
    int lane = threadIdx.x & 31;
    int gw   = cta * 16 + (threadIdx.x >> 5);
    int nw   = nctas * 16;
    for (int e = gw; e < Ee; e += nw) {
        int dst = __ldg(&ei[Ee + e]);
        int src = __ldg(&ei[e]);
        float v0 = __fmul_rn(__ldg(&ea[3 * e + 0]), 2.0f);
        float v1 = __fmul_rn(__ldg(&ea[3 * e + 1]), 2.0f);
        float v2 = __fmul_rn(__ldg(&ea[3 * e + 2]), 2.0f);
        float k0 = fminf(fmaxf(floorf(v0), 0.f), 1.f);
        float k1 = fminf(fmaxf(floorf(v1), 0.f), 1.f);
        float k2 = fminf(fmaxf(floorf(v2), 0.f), 1.f);
        float f0 = v0 - k0, f1 = v1 - k1, f2 = v2 - k2;
        int pb = (int)k0 * 9 + (int)k1 * 3 + (int)k2;
        float xj0 = __ldg(&x[(size_t)src * KIN + lane]);
        float xj1 = __ldg(&x[(size_t)src * KIN + 32 + lane]);
        float* accb = g_accN + (size_t)dst * PIN;
        #pragma unroll
        for (int s = 0; s < 8; ++s) {
            int b0 = s & 1, b1 = (s >> 1) & 1, b2 = (s >> 2) & 1;
            float b = b0 ? f0 : (1.0f - f0);
            b = __fmul_rn(b, b1 ? f1 : (1.0f - f1));
            b = __fmul_rn(b, b2 ? f2 : (1.0f - f2));
            int off = (pb + b0 * 9 + b1 * 3 + b2) * KIN;
            atomicAdd(&accb[off + lane],      __fmul_rn(b, xj0));
            atomicAdd(&accb[off + 32 + lane], __fmul_rn(b, xj1));
        }
        if (lane == 0) atomicAdd(&g_degN[dst], 1.0f);
    }
}

// ---------------- launch 4 (FAT): blocks 0-1 = FPS cluster, 2-143 = scatter ----------------
__global__ void __launch_bounds__(512, 1) __cluster_dims__(CL, 1, 1)
fat_kernel(const float* __restrict__ x,
           const int*   __restrict__ ei,
           const float* __restrict__ ea) {
    extern __shared__ unsigned char s_raw[];
    if (blockIdx.x < CL) fps_cluster(s_raw);
    else scatter_all(x, ei, ea, blockIdx.x - CL, gridDim.x - CL);
}

// ---------------- launch 5: gather-GEMM + root + bias + ELU (20 nodes/block) ----------------
#define NB 20
__global__ void __launch_bounds__(64) node_out_kernel(const float* __restrict__ x,
                                                      const float* __restrict__ W,
                                                      const float* __restrict__ rootw,
                                                      const float* __restrict__ bias,
                                                      float* __restrict__ out) {
    int m0 = blockIdx.x * NB;
    int o  = threadIdx.x;
    int nodes[NB];
    #pragma unroll
    for (int j = 0; j < NB; ++j) nodes[j] = g_idx[m0 + j];
    float s[NB];
    #pragma unroll
    for (int j = 0; j < NB; ++j) s[j] = 0.f;
    #pragma unroll 2
    for (int k = 0; k < PIN; ++k) {
        float w = __ldg(&W[k * KIN + o]);
        #pragma unroll
        for (int j = 0; j < NB; ++j)
            s[j] += __ldg(&g_accN[(size_t)nodes[j] * PIN + k]) * w;
    }
    float b = bias[o];
    for (int j = 0; j < NB; ++j) {
        int m = m0 + j;
        float v = s[j] / fmaxf(g_degN[nodes[j]], 1.0f);
        const float* xr = x + (size_t)nodes[j] * KIN;
        #pragma unroll 8
        for (int i = 0; i < KIN; ++i)
            v += __ldg(&xr[i]) * __ldg(&rootw[i * KIN + o]);
        v += b;
        v = (v > 0.f) ? v : expm1f(v);
        out[SEC_X + m * KIN + o] = v;
    }
}

// ---------------- launch 6: radius via grid + bitmap + fused tail gathers ----------------
#define RW 625
__global__ void __launch_bounds__(128) radius_kernel(const float* __restrict__ ea,
                                                     float* __restrict__ out) {
    __shared__ unsigned s_bm[RW];
    __shared__ int s_cells[32];
    __shared__ int s_ncell;
    int m = blockIdx.x, tid = threadIdx.x;
    int node = g_idx[m];
    float4 q = g_pos4[node];
    for (int i = tid; i < RW; i += 128) s_bm[i] = 0u;
    if (tid == 0) {
        int lo[3], hi[3];
        float qc[3] = {q.x, q.y, q.z};
        for (int d = 0; d < 3; ++d) {
            lo[d] = max(0, (int)floorf((qc[d] - 0.1f) * 8.0f - 1e-3f));
            hi[d] = min(7, (int)floorf((qc[d] + 0.1f) * 8.0f + 1e-3f));
        }
        int n = 0;
        for (int cx = lo[0]; cx <= hi[0]; ++cx)
            for (int cy = lo[1]; cy <= hi[1]; ++cy)
                for (int cz = lo[2]; cz <= hi[2]; ++cz)
                    s_cells[n++] = (cx << 6) | (cy << 3) | cz;
        s_ncell = n;
        // fused tail: pos[idx], batch[idx], edge_attr[idx]
        out[SEC_POS + 3 * m + 0] = q.x;
        out[SEC_POS + 3 * m + 1] = q.y;
        out[SEC_POS + 3 * m + 2] = q.z;
        out[SEC_BATCH + m]       = 0.0f;
        out[SEC_EA + 3 * m + 0]  = ea[3 * node + 0];
        out[SEC_EA + 3 * m + 1]  = ea[3 * node + 1];
        out[SEC_EA + 3 * m + 2]  = ea[3 * node + 2];
    }
    __syncthreads();
    int nc = s_ncell;
    for (int ci = 0; ci < nc; ++ci) {
        int cid = s_cells[ci];
        int st = g_cellstart[cid], en = g_cellstart[cid + 1];
        for (int i = st + tid; i < en; i += 128) {
            float4 p = __ldg(&g_spos[i]);
            float an = __fadd_rn(__fadd_rn(__fmul_rn(p.x, p.x), __fmul_rn(p.y, p.y)),
                                 __fmul_rn(p.z, p.z));
            float dot = __fadd_rn(__fadd_rn(__fmul_rn(q.x, p.x), __fmul_rn(q.y, p.y)),
                                  __fmul_rn(q.z, p.z));
            float d2 = __fadd_rn(__fadd_rn(q.w, an), -__fmul_rn(2.0f, dot));
            if (d2 < R2c) {
                int oi = __float_as_int(p.w);
                atomicOr(&s_bm[oi >> 5], 1u << (oi & 31));
            }
        }
    }
    __syncthreads();
    if (tid < 32) {
        int lane = tid;
        int base = 0;
        for (int w0 = 0; w0 < RW; w0 += 32) {
            unsigned word = (w0 + lane < RW) ? s_bm[w0 + lane] : 0u;
            int pc = __popc(word);
            int ex = pc;
            #pragma unroll
            for (int o = 1; o < 32; o <<= 1) {
                int v = __shfl_up_sync(0xffffffffu, ex, o);
                if (lane >= o) ex += v;
            }
            int tot = __shfl_sync(0xffffffffu, ex, 31);
            ex -= pc;
            int pos = base + ex;
            while (word && pos < MAXNb) {
                int b = __ffs(word) - 1;
                word &= word - 1;
                int oi = (w0 + lane) * 32 + b;
                out[SEC_COL + m * MAXNb + pos] = (float)oi;
                out[SEC_ROW + m * MAXNb + pos] = (float)m;
                ++pos;
            }
            base += tot;
            if (base >= MAXNb) break;
        }
        for (int j = base + lane; j < MAXNb; j += 32) {
            out[SEC_COL + m * MAXNb + j] = -1.0f;
            out[SEC_ROW + m * MAXNb + j] = -1.0f;
        }
    }
}

// ---------------- launch ----------------
extern "C" void kernel_launch(void* const* d_in, const int* in_sizes, int n_in,
                              void* d_out, int out_size) {
    const float* x     = (const float*)d_in[0];
    const int*   ei    = (const int*)d_in[1];
    const float* ea    = (const float*)d_in[2];
    const float* pos   = (const float*)d_in[3];
    const float* W     = (const float*)d_in[5];
    const float* rootw = (const float*)d_in[6];
    const float* bias  = (const float*)d_in[7];
    float* out = (float*)d_out;

    cudaFuncSetAttribute(fat_kernel, cudaFuncAttributeMaxDynamicSharedMemorySize,
                         FPS_SMEM);

    prep1b_kernel<<<1, 1024>>>(pos);                 // 1
    cell_scan_kernel<<<1, NC>>>();                   // 2
    scatter_zero_kernel<<<ZB, 256>>>(pos);           // 3
    fat_kernel<<<144, 512, FPS_SMEM>>>(x, ei, ea);   // 4 (ncu target)
    node_out_kernel<<<Mm / NB, KIN>>>(x, W, rootw, bias, out); // 5
    radius_kernel<<<Mm, 128>>>(ea, out);             // 6 (tail fused)
}

// round 17
// speedup vs baseline: 1.0826x; 1.0826x over previous
#include <cuda_runtime.h>
#include <math.h>

// ---------------- problem constants ----------------
#define Nn    20000
#define Ee    640000
#define Pp    27
#define Mm    5000
#define MAXNb 64
#define KIN   64
#define PIN   (Pp * KIN)      // 1728
#define R2c   0.01f
#define NC    512             // 8x8x8 spatial cells
#define CL    2               // FPS cluster size (half the cloud per CTA)
#define SLAB_MAX 10560        // max points per half (mean 10000)

// output section offsets (flattened float32 tuple concat)
#define SEC_X     0
#define SEC_COL   320000
#define SEC_ROW   640000
#define SEC_POS   960000
#define SEC_BATCH 975000
#define SEC_EA    980000

// ---------------- persistent device scratch ----------------
__device__ __align__(16) float4 g_pos4[Nn];   // x,y,z, |p|^2
__device__ int    g_idx[Mm];
__device__ int    g_pcell[Nn];
__device__ int    g_cellcnt[NC];
__device__ int    g_cellstart[NC + 1];
__device__ int    g_cellfill[NC];
__device__ __align__(16) float4 g_spos[Nn];   // cell-sorted: x,y,z, orig idx bits
__device__ __align__(16) float g_accN[(size_t)Nn * PIN];  // 138 MB, all nodes
__device__ float  g_degN[Nn];

// ---------------- launch 1: pos4 + cell id + histogram + scan (single block) ----------
__global__ void __launch_bounds__(1024) prep_scan_kernel(const float* __restrict__ pos) {
    __shared__ int sh[NC];
    int tid = threadIdx.x;
    if (tid < NC) g_cellcnt[tid] = 0;
    __syncthreads();
    for (int i = tid; i < Nn; i += 1024) {
        float x = pos[3 * i], y = pos[3 * i + 1], z = pos[3 * i + 2];
        float an = __fadd_rn(__fadd_rn(__fmul_rn(x, x), __fmul_rn(y, y)),
                             __fmul_rn(z, z));
        g_pos4[i] = make_float4(x, y, z, an);
        int cx = min((int)(x * 8.0f), 7);
        int cy = min((int)(y * 8.0f), 7);
        int cz = min((int)(z * 8.0f), 7);
        int cid = (cx << 6) | (cy << 3) | cz;
        g_pcell[i] = cid;
        atomicAdd(&g_cellcnt[cid], 1);
    }
    __syncthreads();
    // inclusive scan over 512 counts (threads 0-511 participate)
    int v = 0;
    if (tid < NC) { v = g_cellcnt[tid]; sh[tid] = v; }
    __syncthreads();
    for (int o = 1; o < NC; o <<= 1) {
        int t = (tid < NC && tid >= o) ? sh[tid - o] : 0;
        __syncthreads();
        if (tid < NC) sh[tid] += t;
        __syncthreads();
    }
    if (tid < NC) {
        g_cellstart[tid + 1] = sh[tid];
        g_cellfill[tid] = sh[tid] - v;
    }
    if (tid == 0) g_cellstart[0] = 0;
}

// ---------------- launch 2: cell scatter + zero acc/deg (fused) ----------------
#define ZB 33750   // 33750*256 float4 = Nn*PIN floats
__global__ void scatter_zero_kernel(const float* __restrict__ pos) {
    int i = blockIdx.x * blockDim.x + threadIdx.x;
    if (i < Nn) {
        int cid = g_pcell[i];
        int off = atomicAdd(&g_cellfill[cid], 1);
        g_spos[off] = make_float4(pos[3 * i], pos[3 * i + 1], pos[3 * i + 2],
                                  __int_as_float(i));
        g_degN[i] = 0.0f;
    }
    reinterpret_cast<float4*>(g_accN)[i] = make_float4(0.f, 0.f, 0.f, 0.f);
}

// ---------------- FPS cluster helpers ----------------
__device__ __forceinline__ unsigned smem_u32(const void* p) {
    unsigned a;
    asm("{ .reg .u64 t; cvta.to.shared.u64 t, %1; cvt.u32.u64 %0, t; }"
        : "=r"(a) : "l"(p));
    return a;
}
__device__ __forceinline__ unsigned cl_rank() {
    unsigned r;
    asm("mov.u32 %0, %%cluster_ctarank;" : "=r"(r));
    return r;
}
#define CL_SYNC() do { \
    asm volatile("barrier.cluster.arrive.aligned;" ::: "memory"); \
    asm volatile("barrier.cluster.wait.aligned;" ::: "memory"); } while (0)

// polling wait (R15 form — measured faster than HW-sleep hint at this granularity)
#define MBAR_WAIT_CLUSTER(mbar, par) do { \
    asm volatile("{\n\t.reg .pred p;\n\t" \
        "WAITC_%=:\n\t" \
        "mbarrier.try_wait.parity.acquire.cluster.shared::cta.b64 p, [%0], %1;\n\t" \
        "@p bra.uni DONEC_%=;\n\t" \
        "bra.uni WAITC_%=;\n\t" \
        "DONEC_%=:\n\t}" :: "r"(mbar), "r"(par) : "memory"); } while (0)

// ---------------- FPS SMEM layout (2-CTA, half cloud resident) ----------------
#define OFF_PT     0u                         // SLAB_MAX*16 = 168960
#define OFF_MIND   168960u                    // SLAB_MAX*4  = 42240
#define OFF_CST    211200u                    // 257*4 -> pad 1040
#define OFF_SKEY   212240u                    // 2 bufs * 32 slots * u64 = 512
#define OFF_SPOS   212752u                    // 2 bufs * 32 slots * float4 = 1024
#define OFF_MBAR   213776u                    // 2 mbarriers = 16
#define FPS_SMEM   213792u

// ---------------- FPS body: 2-CTA cluster, warp-direct exchange (R15) ----------------
__device__ void fps_cluster(unsigned char* s_raw) {
    float4*             s_pt   = (float4*)(s_raw + OFF_PT);
    float*              s_mind = (float*)(s_raw + OFF_MIND);
    int*                s_cst  = (int*)(s_raw + OFF_CST);
    unsigned long long* s_skey = (unsigned long long*)(s_raw + OFF_SKEY);
    float4*             s_spos = (float4*)(s_raw + OFF_SPOS);

    const int tid = threadIdx.x, lane = tid & 31, wid = tid >> 5;
    const unsigned FULL = 0xffffffffu;
    const float INF = __int_as_float(0x7f800000);
    const unsigned rank = cl_rank();
    const int slotid = (int)rank * 16 + wid;      // this warp's global slot

    const unsigned mbar_l = smem_u32(s_raw + OFF_MBAR);
    const unsigned skey_l = smem_u32(s_raw + OFF_SKEY);
    const unsigned spos_l = smem_u32(s_raw + OFF_SPOS);
    unsigned mbar_r, skey_r, spos_r;              // peer addresses (hoisted mapa)
    asm("mapa.shared::cluster.u32 %0, %1, %2;" : "=r"(mbar_r) : "r"(mbar_l), "r"(rank ^ 1u));
    asm("mapa.shared::cluster.u32 %0, %1, %2;" : "=r"(skey_r) : "r"(skey_l), "r"(rank ^ 1u));
    asm("mapa.shared::cluster.u32 %0, %1, %2;" : "=r"(spos_r) : "r"(spos_l), "r"(rank ^ 1u));

    // ---- per-lane owned cell (bijective balanced map: 16 cells/warp) ----
    int l   = lane & 15;
    int cx4 = l >> 2, cyi = l & 3;
    int cz  = ((wid & 7) - 2 * cx4) & 7;
    int par0 = ((wid >> 3) ^ cx4) & 1;
    int cy  = 2 * cyi + par0;
    int cid = (cx4 << 6) | (cy << 3) | cz;
    const float lx = (float)((int)rank * 4 + cx4) * 0.125f;
    const float ly = (float)cy * 0.125f;
    const float lz = (float)cz * 0.125f;

    // ---- init: load half-cloud into SMEM ----
    int base  = g_cellstart[rank * 256];
    int count = min(g_cellstart[rank * 256 + 256] - base, SLAB_MAX);
    if (tid <= 256)
        s_cst[tid] = min(g_cellstart[rank * 256 + tid] - base, SLAB_MAX);
    for (int i = tid; i < count; i += 512) {
        s_pt[i] = g_spos[base + i];
        s_mind[i] = INF;
    }
    __syncthreads();
    const int st_l = s_cst[cid], en_l = s_cst[cid + 1];
    unsigned long long ukey =
        (lane < 16 && en_l > st_l) ? (0x7f800000ULL << 32) : 0ULL;
    float uwx = 0.f, uwy = 0.f, uwz = 0.f;
    if (tid == 0) {
        asm volatile("mbarrier.init.shared.b64 [%0], %1;" :: "r"(mbar_l),     "r"(32) : "memory");
        asm volatile("mbarrier.init.shared.b64 [%0], %1;" :: "r"(mbar_l + 8), "r"(32) : "memory");
        if (rank == 0) g_idx[0] = 0;
    }
    __syncthreads();
    CL_SYNC();

    float4 q0 = g_pos4[0];
    float qx = q0.x, qy = q0.y, qz = q0.z;

    for (int t = 0; t < Mm - 1; ++t) {
        const int buf = t & 1;
        const int parity = (t >> 1) & 1;
        // ---- activity over this warp's 16 register cells ----
        float dx = fmaxf(fmaxf(lx - qx, qx - (lx + 0.125f)), 0.0f);
        float dy = fmaxf(fmaxf(ly - qy, qy - (ly + 0.125f)), 0.0f);
        float dz = fmaxf(fmaxf(lz - qz, qz - (lz + 0.125f)), 0.0f);
        float lb2 = dx * dx + dy * dy + dz * dz;
        float ub = __uint_as_float((unsigned)(ukey >> 32));
        bool act = (lane < 16) && (lb2 * 0.99999f < ub);
        unsigned bal = __ballot_sync(FULL, act);
        // ---- update active cells (whole warp per cell; keys/pos in regs) ----
        while (bal) {
            int i = __ffs(bal) - 1; bal &= bal - 1;
            int st = __shfl_sync(FULL, st_l, i);
            int en = __shfl_sync(FULL, en_l, i);
            float bv = -1.0f; int bidx = 0x7FFFFFFF;
            float bx = 0.f, by = 0.f, bz = 0.f;
            for (int k = st + lane; k < en; k += 32) {
                float4 p = s_pt[k];
                float ddx = p.x - qx, ddy = p.y - qy, ddz = p.z - qz;
                float d2 = __fadd_rn(__fadd_rn(__fmul_rn(ddx, ddx),
                                               __fmul_rn(ddy, ddy)),
                                     __fmul_rn(ddz, ddz));
                float nm = fminf(s_mind[k], d2);
                s_mind[k] = nm;
                int oi = __float_as_int(p.w);
                if (nm > bv || (nm == bv && oi < bidx)) {
                    bv = nm; bidx = oi; bx = p.x; by = p.y; bz = p.z;
                }
            }
            unsigned vb = (bv < 0.f) ? 0u : __float_as_uint(bv);
            unsigned mv = __reduce_max_sync(FULL, vb);
            unsigned ciw = (vb == mv) ? (unsigned)bidx : 0xFFFFFFFFu;
            unsigned mi = __reduce_min_sync(FULL, ciw);
            int wl = __ffs(__ballot_sync(FULL, vb == mv && (unsigned)bidx == mi)) - 1;
            float px = __shfl_sync(FULL, bx, wl);
            float py = __shfl_sync(FULL, by, wl);
            float pz = __shfl_sync(FULL, bz, wl);
            if (lane == i) {
                ukey = ((unsigned long long)mv << 32) |
                       (unsigned long long)(0xFFFFFFFFu - mi);
                uwx = px; uwy = py; uwz = pz;
            }
        }
        // ---- warp best over 32 register keys -> write BOTH CTAs' slots ----
        {
            unsigned hi = (unsigned)(ukey >> 32), lo = (unsigned)ukey;
            unsigned mhi = __reduce_max_sync(FULL, hi);
            unsigned lo2 = (hi == mhi) ? lo : 0u;
            unsigned mlo = __reduce_max_sync(FULL, lo2);
            unsigned long long wbest = ((unsigned long long)mhi << 32) | mlo;
            int wl = __ffs(__ballot_sync(FULL, ukey == wbest)) - 1;
            if (lane == wl) {
                int si = buf * 32 + slotid;
                s_skey[si] = wbest;
                s_spos[si] = make_float4(uwx, uwy, uwz, 0.f);
                unsigned rk = skey_r + (unsigned)si * 8u;
                unsigned rp = spos_r + (unsigned)si * 16u;
                unsigned long long xy =
                    ((unsigned long long)__float_as_uint(uwy) << 32) |
                    (unsigned long long)__float_as_uint(uwx);
                asm volatile("st.shared::cluster.u64 [%0], %1;" :: "r"(rk), "l"(wbest) : "memory");
                asm volatile("st.shared::cluster.u64 [%0], %1;" :: "r"(rp), "l"(xy) : "memory");
                asm volatile("st.shared::cluster.b32 [%0], %1;"
                             :: "r"(rp + 8), "r"(__float_as_uint(uwz)) : "memory");
                asm volatile("mbarrier.arrive.release.cluster.shared::cluster.b64 _, [%0];"
                             :: "r"(mbar_r + (unsigned)buf * 8u) : "memory");
                asm volatile("mbarrier.arrive.shared.b64 _, [%0];"
                             :: "r"(mbar_l + (unsigned)buf * 8u) : "memory");
            }
        }
        // ---- wait for all 32 warp-arrives (16 local + 16 remote), combine ----
        MBAR_WAIT_CLUSTER(mbar_l + (unsigned)buf * 8u, parity);
        unsigned long long k = s_skey[buf * 32 + lane];
        unsigned hi = (unsigned)(k >> 32), lo = (unsigned)k;
        unsigned mhi = __reduce_max_sync(FULL, hi);
        unsigned lo2 = (hi == mhi) ? lo : 0u;
        unsigned mlo = __reduce_max_sync(FULL, lo2);
        unsigned long long best = ((unsigned long long)mhi << 32) | mlo;
        int b = __ffs(__ballot_sync(FULL, k == best)) - 1;
        float4 wq = s_spos[buf * 32 + b];
        qx = wq.x; qy = wq.y; qz = wq.z;
        if (rank == 0 && tid == 0)
            g_idx[t + 1] = (int)(0xFFFFFFFFu - mlo);
    }

    // ---- teardown: inval mbarriers for graph-replay safety ----
    __syncthreads();
    CL_SYNC();
    if (tid == 0) {
        asm volatile("mbarrier.inval.shared.b64 [%0];" :: "r"(mbar_l)     : "memory");
        asm volatile("mbarrier.inval.shared.b64 [%0];" :: "r"(mbar_l + 8) : "memory");
    }
    __syncthreads();
    CL_SYNC();
}

// ---------------- scatter body: all edges, all nodes, warp per edge ----------------
__device__ void scatter_all(const float* __restrict__ x,
                            const int*   __restrict__ ei,
                            const float* __restrict__ ea,
                            int cta, int nctas) {
    int lane = threadIdx.x & 31;
    int gw   = cta * 16 + (threadIdx.x >> 5);
    int nw   = nctas * 16;
    for (int e = gw; e < Ee; e += nw) {
        int dst = __ldg(&ei[Ee + e]);
        int src = __ldg(&ei[e]);
        float v0 = __fmul_rn(__ldg(&ea[3 * e + 0]), 2.0f);
        float v1 = __fmul_rn(__ldg(&ea[3 * e + 1]), 2.0f);
        float v2 = __fmul_rn(__ldg(&ea[3 * e + 2]), 2.0f);
        float k0 = fminf(fmaxf(floorf(v0), 0.f), 1.f);
        float k1 = fminf(fmaxf(floorf(v1), 0.f), 1.f);
        float k2 = fminf(fmaxf(floorf(v2), 0.f), 1.f);
        float f0 = v0 - k0, f1 = v1 - k1, f2 = v2 - k2;
        int pb = (int)k0 * 9 + (int)k1 * 3 + (int)k2;
        float xj0 = __ldg(&x[(size_t)src * KIN + lane]);
        float xj1 = __ldg(&x[(size_t)src * KIN + 32 + lane]);
        float* accb = g_accN + (size_t)dst * PIN;
        #pragma unroll
        for (int s = 0; s < 8; ++s) {
            int b0 = s & 1, b1 = (s >> 1) & 1, b2 = (s >> 2) & 1;
            float b = b0 ? f0 : (1.0f - f0);
            b = __fmul_rn(b, b1 ? f1 : (1.0f - f1));
            b = __fmul_rn(b, b2 ? f2 : (1.0f - f2));
            int off = (pb + b0 * 9 + b1 * 3 + b2) * KIN;
            atomicAdd(&accb[off + lane],      __fmul_rn(b, xj0));
            atomicAdd(&accb[off + 32 + lane], __fmul_rn(b, xj1));
        }
        if (lane == 0) atomicAdd(&g_degN[dst], 1.0f);
    }
}

// ---------------- launch 3 (FAT): blocks 0-1 = FPS cluster, 2-143 = scatter ----------------
__global__ void __launch_bounds__(512, 1) __cluster_dims__(CL, 1, 1)
fat_kernel(const float* __restrict__ x,
           const int*   __restrict__ ei,
           const float* __restrict__ ea) {
    extern __shared__ unsigned char s_raw[];
    if (blockIdx.x < CL) fps_cluster(s_raw);
    else scatter_all(x, ei, ea, blockIdx.x - CL, gridDim.x - CL);
}

// ---------------- launch 4: fused node_out (blocks 0-249) + radius/tail (250+) ----------
#define NB 20
#define RW 625
#define NOB (Mm / NB)   // 250

__device__ void node_out_body(const float* __restrict__ x,
                              const float* __restrict__ W,
                              const float* __restrict__ rootw,
                              const float* __restrict__ bias,
                              float* __restrict__ out, int blk) {
    int half = threadIdx.x >> 6;          // 0 or 1: handles 10 nodes each
    int o    = threadIdx.x & 63;
    int m0 = blk * NB + half * (NB / 2);
    int nodes[NB / 2];
    #pragma unroll
    for (int j = 0; j < NB / 2; ++j) nodes[j] = g_idx[m0 + j];
    float s[NB / 2];
    #pragma unroll
    for (int j = 0; j < NB / 2; ++j) s[j] = 0.f;
    #pragma unroll 2
    for (int k = 0; k < PIN; ++k) {
        float w = __ldg(&W[k * KIN + o]);
        #pragma unroll
        for (int j = 0; j < NB / 2; ++j)
            s[j] += __ldg(&g_accN[(size_t)nodes[j] * PIN + k]) * w;
    }
    float b = bias[o];
    for (int j = 0; j < NB / 2; ++j) {
        int m = m0 + j;
        float v = s[j] / fmaxf(g_degN[nodes[j]], 1.0f);
        const float* xr = x + (size_t)nodes[j] * KIN;
        #pragma unroll 8
        for (int i = 0; i < KIN; ++i)
            v += __ldg(&xr[i]) * __ldg(&rootw[i * KIN + o]);
        v += b;
        v = (v > 0.f) ? v : expm1f(v);
        out[SEC_X + m * KIN + o] = v;
    }
}

__global__ void __launch_bounds__(128) out_kernel(const float* __restrict__ x,
                                                  const float* __restrict__ W,
                                                  const float* __restrict__ rootw,
                                                  const float* __restrict__ bias,
                                                  const float* __restrict__ ea,
                                                  float* __restrict__ out) {
    __shared__ unsigned s_bm[RW];
    __shared__ int s_cells[32];
    __shared__ int s_ncell;
    if (blockIdx.x < NOB) {
        node_out_body(x, W, rootw, bias, out, blockIdx.x);
        return;
    }
    int m = blockIdx.x - NOB, tid = threadIdx.x;
    int node = g_idx[m];
    float4 q = g_pos4[node];
    for (int i = tid; i < RW; i += 128) s_bm[i] = 0u;
    if (tid == 0) {
        int lo[3], hi[3];
        float qc[3] = {q.x, q.y, q.z};
        for (int d = 0; d < 3; ++d) {
            lo[d] = max(0, (int)floorf((qc[d] - 0.1f) * 8.0f - 1e-3f));
            hi[d] = min(7, (int)floorf((qc[d] + 0.1f) * 8.0f + 1e-3f));
        }
        int n = 0;
        for (int cx = lo[0]; cx <= hi[0]; ++cx)
            for (int cy = lo[1]; cy <= hi[1]; ++cy)
                for (int cz = lo[2]; cz <= hi[2]; ++cz)
                    s_cells[n++] = (cx << 6) | (cy << 3) | cz;
        s_ncell = n;
        out[SEC_POS + 3 * m + 0] = q.x;
        out[SEC_POS + 3 * m + 1] = q.y;
        out[SEC_POS + 3 * m + 2] = q.z;
        out[SEC_BATCH + m]       = 0.0f;
        out[SEC_EA + 3 * m + 0]  = ea[3 * node + 0];
        out[SEC_EA + 3 * m + 1]  = ea[3 * node + 1];
        out[SEC_EA + 3 * m + 2]  = ea[3 * node + 2];
    }
    __syncthreads();
    int nc = s_ncell;
    for (int ci = 0; ci < nc; ++ci) {
        int cid = s_cells[ci];
        int st = g_cellstart[cid], en = g_cellstart[cid + 1];
        for (int i = st + tid; i < en; i += 128) {
            float4 p = __ldg(&g_spos[i]);
            float an = __fadd_rn(__fadd_rn(__fmul_rn(p.x, p.x), __fmul_rn(p.y, p.y)),
                                 __fmul_rn(p.z, p.z));
            float dot = __fadd_rn(__fadd_rn(__fmul_rn(q.x, p.x), __fmul_rn(q.y, p.y)),
                                  __fmul_rn(q.z, p.z));
            float d2 = __fadd_rn(__fadd_rn(q.w, an), -__fmul_rn(2.0f, dot));
            if (d2 < R2c) {
                int oi = __float_as_int(p.w);
                atomicOr(&s_bm[oi >> 5], 1u << (oi & 31));
            }
        }
    }
    __syncthreads();
    if (tid < 32) {
        int lane = tid;
        int basei = 0;
        for (int w0 = 0; w0 < RW; w0 += 32) {
            unsigned word = (w0 + lane < RW) ? s_bm[w0 + lane] : 0u;
            int pc = __popc(word);
            int ex = pc;
            #pragma unroll
            for (int o = 1; o < 32; o <<= 1) {
                int v = __shfl_up_sync(0xffffffffu, ex, o);
                if (lane >= o) ex += v;
            }
            int tot = __shfl_sync(0xffffffffu, ex, 31);
            ex -= pc;
            int pos = basei + ex;
            while (word && pos < MAXNb) {
                int b = __ffs(word) - 1;
                word &= word - 1;
                int oi = (w0 + lane) * 32 + b;
                out[SEC_COL + m * MAXNb + pos] = (float)oi;
                out[SEC_ROW + m * MAXNb + pos] = (float)m;
                ++pos;
            }
            basei += tot;
            if (basei >= MAXNb) break;
        }
        for (int j = basei + lane; j < MAXNb; j += 32) {
            out[SEC_COL + m * MAXNb + j] = -1.0f;
            out[SEC_ROW + m * MAXNb + j] = -1.0f;
        }
    }
}

// ---------------- launch ----------------
extern "C" void kernel_launch(void* const* d_in, const int* in_sizes, int n_in,
                              void* d_out, int out_size) {
    const float* x     = (const float*)d_in[0];
    const int*   ei    = (const int*)d_in[1];
    const float* ea    = (const float*)d_in[2];
    const float* pos   = (const float*)d_in[3];
    const float* W     = (const float*)d_in[5];
    const float* rootw = (const float*)d_in[6];
    const float* bias  = (const float*)d_in[7];
    float* out = (float*)d_out;

    cudaFuncSetAttribute(fat_kernel, cudaFuncAttributeMaxDynamicSharedMemorySize,
                         FPS_SMEM);

    prep_scan_kernel<<<1, 1024>>>(pos);              // 1 (hist + scan fused)
    scatter_zero_kernel<<<ZB, 256>>>(pos);           // 2
    fat_kernel<<<144, 512, FPS_SMEM>>>(x, ei, ea);   // 3
    out_kernel<<<NOB + Mm, 128>>>(x, W, rootw, bias, ea, out);  // 4 (fused)
}